// round 15
// baseline (speedup 1.0000x reference)
#include <cuda_runtime.h>

// -------------------------------------------------------------------------
// out = Conv2(ReLU(Conv1( sum_t Ht[t,:,:] * upsample4(yt[b,t]) )))
//   yt:(32,32,64,64) Ht:(32,256,256) W1:(32,1,3,3) b1:(32) W2:(1,32,3,3) b2:(1)
//   out:(32,1,256,256) f32
// -------------------------------------------------------------------------

#define B_ 32
#define T_ 32
#define R_ 256

typedef unsigned long long u64;

__device__ float g_x[B_ * R_ * R_];   // stage-1 scratch (8.4 MB static)

__device__ __forceinline__ u64 pk2(float lo, float hi) {
    u64 r; asm("mov.b64 %0, {%1,%2};" : "=l"(r) : "f"(lo), "f"(hi)); return r;
}
__device__ __forceinline__ float2 upk2(u64 a) {
    float2 v; asm("mov.b64 {%0,%1}, %2;" : "=f"(v.x), "=f"(v.y) : "l"(a)); return v;
}
__device__ __forceinline__ u64 ffma2(u64 a, u64 b, u64 c) {
    u64 d; asm("fma.rn.f32x2 %0, %1, %2, %3;" : "=l"(d) : "l"(a), "l"(b), "l"(c)); return d;
}
__device__ __forceinline__ u64 fadd2(u64 a, u64 b) {
    u64 d; asm("add.rn.f32x2 %0, %1, %2;" : "=l"(d) : "l"(a), "l"(b)); return d;
}

// ---------------- Stage 1: 4 pixels per thread, vectorized ----------------
__global__ void __launch_bounds__(256) stage1_kernel(
    const float* __restrict__ yt, const float* __restrict__ Ht)
{
    int tid  = threadIdx.x;
    int bx   = blockIdx.x;
    int t64  = tid & 63;
    int prow = tid >> 6;
    int p    = (bx << 2) + prow;
    int idx  = (p << 8) + (t64 << 2);
    int yoff = (bx << 6) + t64;

    int bbase = blockIdx.y << 3;
    float4 acc[8];
#pragma unroll
    for (int bo = 0; bo < 8; bo++) acc[bo] = make_float4(0.f, 0.f, 0.f, 0.f);

    const float* ytbase = yt + ((long)bbase << 17) + yoff;
#pragma unroll
    for (int t = 0; t < T_; t++) {
        float4 h4 = *(const float4*)(Ht + (t << 16) + idx);
        const float* ytp = ytbase + (t << 12);
#pragma unroll
        for (int bo = 0; bo < 8; bo++) {
            float yv = ytp[(long)bo << 17];
            acc[bo].x = fmaf(h4.x, yv, acc[bo].x);
            acc[bo].y = fmaf(h4.y, yv, acc[bo].y);
            acc[bo].z = fmaf(h4.z, yv, acc[bo].z);
            acc[bo].w = fmaf(h4.w, yv, acc[bo].w);
        }
    }
#pragma unroll
    for (int bo = 0; bo < 8; bo++)
        *(float4*)(g_x + ((long)(bbase + bo) << 16) + idx) = acc[bo];
}

// ---------------- Stage 2: fused conv1+relu+conv2 ----------------
// sh holds channel-PAIR-interleaved h1: [4 pairs][34 rows][36 px * 2 ch]
#define SHW2 72
#define SH_ELEMS (4 * 34 * SHW2)    // 9792 floats = 39168 B
#define SX_ELEMS (36 * 40)          // 5760 B

__global__ void __launch_bounds__(256, 3) fused_conv_kernel(
    const float* __restrict__ W1, const float* __restrict__ b1,
    const float* __restrict__ W2, const float* __restrict__ b2,
    float* __restrict__ out)
{
    __shared__ __align__(16) float sh[SH_ELEMS];
    __shared__ __align__(16) float sx[SX_ELEMS];
    __shared__ float sw1[288];
    __shared__ float sb1[32];
    __shared__ u64  sw2p[144];       // (w_ch0, w_ch1) per pair, 16 pairs x 9

    int tid = threadIdx.x;
    int b   = blockIdx.y;
    int P0  = (blockIdx.x >> 3) << 5;
    int Q0  = (blockIdx.x & 7)  << 5;
    const float* xb = g_x + ((long)b << 16);

    // ---- stage weights + x tile ----
    for (int i = tid; i < 288; i += 256) sw1[i] = W1[i];
    if (tid < 144) {
        int cp = tid / 9, k = tid - cp * 9;
        sw2p[tid] = pk2(W2[(cp << 1) * 9 + k], W2[((cp << 1) + 1) * 9 + k]);
    }
    if (tid < 32) sb1[tid] = b1[tid];
    for (int i = tid; i < SX_ELEMS; i += 256) {
        int r  = i / 40;
        int cc = i - r * 40;
        int gp = P0 - 2 + r;
        int gq = Q0 - 2 + cc;
        float v = 0.f;
        if (cc < 36 && (unsigned)gp < 256u && (unsigned)gq < 256u)
            v = xb[(gp << 8) + gq];
        sx[i] = v;
    }
    __syncthreads();

    // conv1 mapping: (channel-pair, band, strip) = 4 x 7 x 9 = 252 threads
    int p4   = tid / 63;
    int rem  = tid - p4 * 63;
    int d    = rem / 9;
    int s    = rem - d * 9;
    int col  = s << 2;
    int r0   = d * 5;
    bool act = (p4 < 4);
    float cm0 = ((unsigned)(Q0 - 1 + col + 0) < 256u) ? 1.f : 0.f;
    float cm1 = ((unsigned)(Q0 - 1 + col + 1) < 256u) ? 1.f : 0.f;
    float cm2 = ((unsigned)(Q0 - 1 + col + 2) < 256u) ? 1.f : 0.f;
    float cm3 = ((unsigned)(Q0 - 1 + col + 3) < 256u) ? 1.f : 0.f;

    // conv2 mapping: 128 strips (2 rows x 4 cols) x 2 pair-halves (2 pairs each)
    int st   = tid & 127;
    int half = tid >> 7;
    int oy = (st >> 3) << 1;        // 0,2,..,30
    int ox = (st & 7) << 2;         // 0,4,..,28
    float bb = *b2;
    u64 A[4], Bv[4];                // packed (ch-even part, ch-odd part) sums
#pragma unroll
    for (int o = 0; o < 4; o++) {
        A[o]  = (half == 0) ? pk2(bb, 0.f) : 0ull;
        Bv[o] = 0ull;
    }
    if (half == 0) Bv[0] = pk2(bb, 0.f);
    else           Bv[0] = 0ull;
#pragma unroll
    for (int o = 1; o < 4; o++) Bv[o] = 0ull;
    if (half == 0) { Bv[1] = pk2(bb, 0.f); Bv[2] = pk2(bb, 0.f); Bv[3] = pk2(bb, 0.f); }

    for (int g = 0; g < 4; g++) {
        // ===== conv1 + relu: marching rows, 2 channels per thread =====
        if (act) {
            int c0 = (g << 3) + (p4 << 1);
            float w0[9], w1[9];
#pragma unroll
            for (int k = 0; k < 9; k++) { w0[k] = sw1[c0 * 9 + k]; w1[k] = sw1[c0 * 9 + 9 + k]; }
            float bi0 = sb1[c0], bi1 = sb1[c0 + 1];
            float* shp = sh + p4 * (34 * SHW2);
            const float* xp = sx + r0 * 40 + col;

            float v[3][6];
#pragma unroll
            for (int j = 0; j < 2; j++) {
                float4 q4 = *(const float4*)(xp + j * 40);
                float2 q2 = *(const float2*)(xp + j * 40 + 4);
                v[j][0] = q4.x; v[j][1] = q4.y; v[j][2] = q4.z;
                v[j][3] = q4.w; v[j][4] = q2.x; v[j][5] = q2.y;
            }
#pragma unroll
            for (int i = 0; i < 5; i++) {
                int row = r0 + i;
                if (row < 34) {
                    float* vn = v[(i + 2) % 3];
                    {
                        float4 q4 = *(const float4*)(xp + (i + 2) * 40);
                        float2 q2 = *(const float2*)(xp + (i + 2) * 40 + 4);
                        vn[0] = q4.x; vn[1] = q4.y; vn[2] = q4.z;
                        vn[3] = q4.w; vn[4] = q2.x; vn[5] = q2.y;
                    }
                    const float* vr0 = v[i % 3];
                    const float* vr1 = v[(i + 1) % 3];
                    const float* vr2 = v[(i + 2) % 3];
                    float a0 = bi0, a1 = bi0, a2 = bi0, a3 = bi0;
                    float c0a = bi1, c1a = bi1, c2a = bi1, c3a = bi1;
#pragma unroll
                    for (int dx = 0; dx < 3; dx++) {
                        float wa0 = w0[dx], wa1 = w0[3 + dx], wa2 = w0[6 + dx];
                        float wb0 = w1[dx], wb1 = w1[3 + dx], wb2 = w1[6 + dx];
                        float x0 = vr0[dx + 0], x1 = vr0[dx + 1], x2 = vr0[dx + 2], x3 = vr0[dx + 3];
                        a0  = fmaf(wa0, x0, a0);  a1  = fmaf(wa0, x1, a1);
                        a2  = fmaf(wa0, x2, a2);  a3  = fmaf(wa0, x3, a3);
                        c0a = fmaf(wb0, x0, c0a); c1a = fmaf(wb0, x1, c1a);
                        c2a = fmaf(wb0, x2, c2a); c3a = fmaf(wb0, x3, c3a);
                        x0 = vr1[dx + 0]; x1 = vr1[dx + 1]; x2 = vr1[dx + 2]; x3 = vr1[dx + 3];
                        a0  = fmaf(wa1, x0, a0);  a1  = fmaf(wa1, x1, a1);
                        a2  = fmaf(wa1, x2, a2);  a3  = fmaf(wa1, x3, a3);
                        c0a = fmaf(wb1, x0, c0a); c1a = fmaf(wb1, x1, c1a);
                        c2a = fmaf(wb1, x2, c2a); c3a = fmaf(wb1, x3, c3a);
                        x0 = vr2[dx + 0]; x1 = vr2[dx + 1]; x2 = vr2[dx + 2]; x3 = vr2[dx + 3];
                        a0  = fmaf(wa2, x0, a0);  a1  = fmaf(wa2, x1, a1);
                        a2  = fmaf(wa2, x2, a2);  a3  = fmaf(wa2, x3, a3);
                        c0a = fmaf(wb2, x0, c0a); c1a = fmaf(wb2, x1, c1a);
                        c2a = fmaf(wb2, x2, c2a); c3a = fmaf(wb2, x3, c3a);
                    }
                    float mr = ((unsigned)(P0 - 1 + row) < 256u) ? 1.f : 0.f;
                    float m0 = mr * cm0, m1 = mr * cm1, m2 = mr * cm2, m3 = mr * cm3;
                    // channel-pair-interleaved store: (ch0,ch1) per pixel
                    float* dst = shp + row * SHW2 + (col << 1);
                    *(float4*)dst = make_float4(
                        fmaxf(a0, 0.f) * m0, fmaxf(c0a, 0.f) * m0,
                        fmaxf(a1, 0.f) * m1, fmaxf(c1a, 0.f) * m1);
                    *(float4*)(dst + 4) = make_float4(
                        fmaxf(a2, 0.f) * m2, fmaxf(c2a, 0.f) * m2,
                        fmaxf(a3, 0.f) * m3, fmaxf(c3a, 0.f) * m3);
                }
            }
        }
        __syncthreads();

        // ===== conv2: 2x4 outputs, 2 channel-pairs per half, FFMA2 =====
        {
#pragma unroll
            for (int cc = 0; cc < 2; cc++) {
                int lp = (half << 1) + cc;          // local pair 0..3
                int cp = (g << 2) + lp;             // global pair 0..15
                u64 w9[9];
#pragma unroll
                for (int k = 0; k < 9; k++) w9[k] = sw2p[cp * 9 + k];
                const float* hp = sh + lp * (34 * SHW2) + oy * SHW2 + (ox << 1);

#pragma unroll
                for (int j = 0; j < 4; j++) {
                    const float* rp = hp + j * SHW2;
                    ulonglong2 qa = *(const ulonglong2*)rp;        // px0, px1
                    ulonglong2 qb = *(const ulonglong2*)(rp + 4);  // px2, px3
                    ulonglong2 qc = *(const ulonglong2*)(rp + 8);  // px4, px5
                    u64 px0 = qa.x, px1 = qa.y, px2 = qb.x,
                        px3 = qb.y, px4 = qc.x, px5 = qc.y;
                    if (j < 3) {                    // out row 0, dy=j
                        u64 w0 = w9[3 * j], w1 = w9[3 * j + 1], w2 = w9[3 * j + 2];
                        A[0] = ffma2(w0, px0, A[0]); A[0] = ffma2(w1, px1, A[0]); A[0] = ffma2(w2, px2, A[0]);
                        A[1] = ffma2(w0, px1, A[1]); A[1] = ffma2(w1, px2, A[1]); A[1] = ffma2(w2, px3, A[1]);
                        A[2] = ffma2(w0, px2, A[2]); A[2] = ffma2(w1, px3, A[2]); A[2] = ffma2(w2, px4, A[2]);
                        A[3] = ffma2(w0, px3, A[3]); A[3] = ffma2(w1, px4, A[3]); A[3] = ffma2(w2, px5, A[3]);
                    }
                    if (j >= 1) {                   // out row 1, dy=j-1
                        u64 w0 = w9[3 * (j - 1)], w1 = w9[3 * (j - 1) + 1], w2 = w9[3 * (j - 1) + 2];
                        Bv[0] = ffma2(w0, px0, Bv[0]); Bv[0] = ffma2(w1, px1, Bv[0]); Bv[0] = ffma2(w2, px2, Bv[0]);
                        Bv[1] = ffma2(w0, px1, Bv[1]); Bv[1] = ffma2(w1, px2, Bv[1]); Bv[1] = ffma2(w2, px3, Bv[1]);
                        Bv[2] = ffma2(w0, px2, Bv[2]); Bv[2] = ffma2(w1, px3, Bv[2]); Bv[2] = ffma2(w2, px4, Bv[2]);
                        Bv[3] = ffma2(w0, px3, Bv[3]); Bv[3] = ffma2(w1, px4, Bv[3]); Bv[3] = ffma2(w2, px5, Bv[3]);
                    }
                }
            }
        }
        __syncthreads();   // before next group's conv1 overwrites sh
    }

    // ---- combine halves via smem, then horizontal (ch0+ch1) sum ----
    u64* red = (u64*)sx;
    if (half == 1) {
        u64* rp = red + st * 8;
#pragma unroll
        for (int o = 0; o < 4; o++) { rp[o] = A[o]; rp[4 + o] = Bv[o]; }
    }
    __syncthreads();
    if (half == 0) {
        const u64* rp = red + st * 8;
        float r0v[4], r1v[4];
#pragma unroll
        for (int o = 0; o < 4; o++) {
            float2 va = upk2(fadd2(A[o],  rp[o]));
            float2 vb = upk2(fadd2(Bv[o], rp[4 + o]));
            r0v[o] = va.x + va.y;
            r1v[o] = vb.x + vb.y;
        }
        float* ob = out + ((long)b << 16) + ((P0 + oy) << 8) + Q0 + ox;
        *(float4*)ob         = make_float4(r0v[0], r0v[1], r0v[2], r0v[3]);
        *(float4*)(ob + 256) = make_float4(r1v[0], r1v[1], r1v[2], r1v[3]);
    }
}

// -------------------------------------------------------------------------
extern "C" void kernel_launch(void* const* d_in, const int* in_sizes, int n_in,
                              void* d_out, int out_size)
{
    const float* yt = (const float*)d_in[0];
    const float* Ht = (const float*)d_in[1];
    const float* W1 = (const float*)d_in[2];
    const float* b1 = (const float*)d_in[3];
    const float* W2 = (const float*)d_in[4];
    const float* b2 = (const float*)d_in[5];
    float* out = (float*)d_out;

    stage1_kernel<<<dim3(64, 4), 256>>>(yt, Ht);
    fused_conv_kernel<<<dim3(64, 32), 256>>>(W1, b1, W2, b2, out);
}